// round 7
// baseline (speedup 1.0000x reference)
#include <cuda_runtime.h>
#include <stdint.h>

// ---------------------------------------------------------------------------
// CoralLoss: mean over (B, K-1) of softplus(s), s = (target > k) ? -x : x
// Fully FMA-pipe softplus (no MUFU): 2^-a via magic-round + deg-5 poly,
// ln(1+u) via deg-5 minimax on [0,1]. Abs err per element ~1e-5.
// ---------------------------------------------------------------------------

#define NBLK 4736
#define NTHR 256

__device__ float g_partial[NBLK];
__device__ int   g_is64;

// Detect whether targets buffer is int64 (odd 32-bit words all zero) or int32.
// Reads only the first 1024 int32 words (safe for either dtype: >= 2 MiB buffer).
__global__ void coral_detect(const int* __restrict__ t32) {
    int tid = threadIdx.x;
    int ok = 1;
    ok &= (t32[2 * tid + 1] == 0);
    ok &= (t32[2 * (tid + 256) + 1] == 0);
    __shared__ int sh[NTHR];
    sh[tid] = ok;
    __syncthreads();
    for (int w = NTHR / 2; w > 0; w >>= 1) {
        if (tid < w) sh[tid] &= sh[tid + w];
        __syncthreads();
    }
    if (tid == 0) g_is64 = sh[0];
}

// softplus(s) = max(s,0) + ln(1 + 2^(-|s|*log2e)), all on fma/alu pipes.
__device__ __forceinline__ float softplus_f(float s) {
    const float LOG2E = 1.4426950408889634f;
    const float MAGIC = 12582912.0f;  // 1.5 * 2^23

    float r0 = fmaxf(s, 0.0f);
    float a  = fminf(fabsf(s) * LOG2E, 30.0f);     // a in [0, 30]
    float zz = MAGIC - a;                           // low bits hold round(-a)
    float kf = zz - MAGIC;                          // = round(-a), exact
    float f  = -(a + kf);                           // frac in [-0.5, 0.5]
    int   ib = (__float_as_int(zz) << 23) + 0x3F800000;  // bits of 2^round(-a)

    // 2^f, f in [-0.5, 0.5]: degree-5 Taylor (rel err ~2e-6)
    float p = fmaf(f, 0.0013333558f, 0.0096181291f);
    p = fmaf(f, p, 0.0555041087f);
    p = fmaf(f, p, 0.2402265069f);
    p = fmaf(f, p, 0.6931471806f);
    p = fmaf(f, p, 1.0f);

    float u = p * __int_as_float(ib);               // u = 2^(-a) in (0, 1]

    // ln(1+u), u in [0,1]: degree-5 Chebyshev-minimax (abs err ~1e-5)
    float l = fmaf(u, 0.03044896f, -0.13158176f);
    l = fmaf(u, l, 0.28527272f);
    l = fmaf(u, l, -0.49023080f);
    l = fmaf(u, l, 0.99923550f);
    l = fmaf(u, l, 1.02e-5f);

    return r0 + l;
}

__global__ void __launch_bounds__(NTHR) coral_main(
    const float4* __restrict__ lg,     // logits viewed as float4, B*16 entries
    const int*    __restrict__ t32,    // targets as int32 words
    int total4)                        // B * 16
{
    const int flag = g_is64;           // 1 -> int64 targets (stride-2 words)
    const int tmul = flag ? 2 : 1;

    float acc = 0.0f;
    const int stride = NBLK * NTHR;
    for (int i = blockIdx.x * NTHR + threadIdx.x; i < total4; i += stride) {
        int row = i >> 4;                  // 16 float4 per row (K-1 = 64)
        int kb  = (i & 15) << 2;           // k index of component .x
        int tgt = t32[row * tmul];
        int d   = tgt - kb;                // component c flips sign iff d > c

        float4 v = lg[i];
        float s0 = (d > 0) ? -v.x : v.x;
        float s1 = (d > 1) ? -v.y : v.y;
        float s2 = (d > 2) ? -v.z : v.z;
        float s3 = (d > 3) ? -v.w : v.w;

        acc += softplus_f(s0);
        acc += softplus_f(s1);
        acc += softplus_f(s2);
        acc += softplus_f(s3);
    }

    // warp reduce
    #pragma unroll
    for (int o = 16; o > 0; o >>= 1)
        acc += __shfl_xor_sync(0xFFFFFFFFu, acc, o);

    __shared__ float sw[NTHR / 32];
    int lane = threadIdx.x & 31;
    int warp = threadIdx.x >> 5;
    if (lane == 0) sw[warp] = acc;
    __syncthreads();
    if (threadIdx.x == 0) {
        float b = 0.0f;
        #pragma unroll
        for (int w = 0; w < NTHR / 32; w++) b += sw[w];
        g_partial[blockIdx.x] = b;
    }
}

__global__ void coral_final(float* __restrict__ out, double inv_n) {
    int tid = threadIdx.x;  // 256 threads
    double a = 0.0;
    for (int i = tid; i < NBLK; i += 256) a += (double)g_partial[i];

    #pragma unroll
    for (int o = 16; o > 0; o >>= 1)
        a += __shfl_xor_sync(0xFFFFFFFFu, a, o);

    __shared__ double sd[8];
    int lane = tid & 31, warp = tid >> 5;
    if (lane == 0) sd[warp] = a;
    __syncthreads();
    if (tid == 0) {
        double s = 0.0;
        #pragma unroll
        for (int w = 0; w < 8; w++) s += sd[w];
        out[0] = (float)(s * inv_n);
    }
}

extern "C" void kernel_launch(void* const* d_in, const int* in_sizes, int n_in,
                              void* d_out, int out_size) {
    const float* logits = (const float*)d_in[0];
    const int*   t32    = (const int*)d_in[1];   // int32 view of targets
    int nelem  = in_sizes[0];                    // B * (K-1) = 33554432
    int total4 = nelem >> 2;                     // float4 count

    coral_detect<<<1, NTHR>>>(t32);
    coral_main<<<NBLK, NTHR>>>((const float4*)logits, t32, total4);
    coral_final<<<1, NTHR>>>((float*)d_out, 1.0 / (double)nelem);
}